// round 7
// baseline (speedup 1.0000x reference)
#include <cuda_runtime.h>
#include <cstdint>

#define Bdim 32
#define Ndim 160
#define NL 25600           // 160*160
#define BC 1024            // 32*32
#define ALPHA 0.05f
#define OMA 0.95f

// ---- scratch (__device__ globals; no allocations). All GEMM operands are
// pre-split (hi,lo) float2 per element. ----
__device__ __align__(16) float  g_A1[Ndim*Ndim];
__device__ __align__(16) float  g_A2[Ndim*Ndim];
__device__ __align__(16) float2 g_Ms2[2*Ndim*Ndim];       // stacked [320][160]
__device__ __align__(16) float2 g_a2[Ndim*Ndim];          // split raw adjacency
__device__ __align__(16) float2 g_Wc2[64*96];             // folded weights
__device__ __align__(16) float2 g_x2[(size_t)BC*NL];      // split x
__device__ __align__(16) float2 g_y2[(size_t)BC*2*NL];    // per bc [320][160]
__device__ __align__(16) float2 g_e2[(size_t)BC*NL];      // embed (split)
__device__ __align__(16) float  g_pool[(size_t)BC*NL];    // raw pool (pre-softmax)
__device__ __align__(16) float2 g_s2[(size_t)BC*NL];      // softmax(pool) split
__device__ __align__(16) float2 g_t2[(size_t)BC*NL];      // s @ a (split)

// ---------- tf32 helpers ----------
__device__ __forceinline__ uint32_t f2tf(float v) {
    uint32_t r; asm("cvt.rna.tf32.f32 %0, %1;" : "=r"(r) : "f"(v)); return r;
}
__device__ __forceinline__ float2 splitf(float v) {
    uint32_t h = f2tf(v);
    uint32_t l = f2tf(v - __uint_as_float(h));
    return make_float2(__uint_as_float(h), __uint_as_float(l));
}
__device__ __forceinline__ void mma8(float* c, const uint32_t* a, const uint32_t* b) {
    asm volatile(
        "mma.sync.aligned.m16n8k8.row.col.f32.tf32.tf32.f32 "
        "{%0,%1,%2,%3}, {%4,%5,%6,%7}, {%8,%9}, {%0,%1,%2,%3};"
        : "+f"(c[0]), "+f"(c[1]), "+f"(c[2]), "+f"(c[3])
        : "r"(a[0]), "r"(a[1]), "r"(a[2]), "r"(a[3]), "r"(b[0]), "r"(b[1]));
}
// ---------- cp.async ----------
__device__ __forceinline__ void cp16(uint32_t saddr, const void* gptr) {
    asm volatile("cp.async.cg.shared.global [%0], [%1], 16;" :: "r"(saddr), "l"(gptr));
}
#define CP_COMMIT() asm volatile("cp.async.commit_group;")
template<int N> __device__ __forceinline__ void cp_wait() {
    asm volatile("cp.async.wait_group %0;" :: "n"(N));
}

// ============================================================
// K1: row-normalized (a+I), (a^T+I); also split copy of raw a
// ============================================================
__global__ void k_norm_adj(const float* __restrict__ a) {
    int v = blockIdx.x;
    int t = threadIdx.x;
    __shared__ float s1[Ndim], s2[Ndim];
    __shared__ float r1, r2;
    float av = a[v*Ndim + t];
    float aw = a[t*Ndim + v];
    s1[t] = av; s2[t] = aw;
    __syncthreads();
    if (t == 0) {
        float x1 = 0.f, x2 = 0.f;
        for (int i = 0; i < Ndim; i++) { x1 += s1[i]; x2 += s2[i]; }
        r1 = x1 + 1.f; r2 = x2 + 1.f;
    }
    __syncthreads();
    float diag = (t == v) ? 1.f : 0.f;
    g_A1[v*Ndim + t] = (av + diag) / r1;
    g_A2[v*Ndim + t] = (aw + diag) / r2;
    g_a2[v*Ndim + t] = splitf(av);
}

// ============================================================
// K2: Mstack (split output)
// ============================================================
__global__ void k_prep() {
    __shared__ float As1[32][36], As2[32][36], Bs1[32][36], Bs2[32][36];
    int tid = threadIdx.x;
    int tx = tid & 7, ty = tid >> 3;
    int bi = blockIdx.y, bj = blockIdx.x;
    float c1[4][4] = {}, c2[4][4] = {};
    for (int kt = 0; kt < 5; kt++) {
        #pragma unroll
        for (int it = 0; it < 4; it++) {
            int g = tid + it*64;
            int m = g >> 3, k4 = g & 7;
            float4 v1 = *(const float4*)&g_A1[(bi*32+m)*Ndim + kt*32 + k4*4];
            float4 v2 = *(const float4*)&g_A2[(bi*32+m)*Ndim + kt*32 + k4*4];
            As1[k4*4+0][m] = v1.x; As1[k4*4+1][m] = v1.y;
            As1[k4*4+2][m] = v1.z; As1[k4*4+3][m] = v1.w;
            As2[k4*4+0][m] = v2.x; As2[k4*4+1][m] = v2.y;
            As2[k4*4+2][m] = v2.z; As2[k4*4+3][m] = v2.w;
            int r = g >> 3, c4 = g & 7;
            *(float4*)&Bs1[r][c4*4] = *(const float4*)&g_A1[(kt*32+r)*Ndim + bj*32 + c4*4];
            *(float4*)&Bs2[r][c4*4] = *(const float4*)&g_A2[(kt*32+r)*Ndim + bj*32 + c4*4];
        }
        __syncthreads();
        #pragma unroll
        for (int k = 0; k < 32; k++) {
            float4 a1 = *(const float4*)&As1[k][ty*4];
            float4 a2 = *(const float4*)&As2[k][ty*4];
            float4 b1 = *(const float4*)&Bs1[k][tx*4];
            float4 b2 = *(const float4*)&Bs2[k][tx*4];
            float aa1[4] = {a1.x,a1.y,a1.z,a1.w}, aa2[4] = {a2.x,a2.y,a2.z,a2.w};
            float bb1[4] = {b1.x,b1.y,b1.z,b1.w}, bb2[4] = {b2.x,b2.y,b2.z,b2.w};
            #pragma unroll
            for (int i = 0; i < 4; i++)
            #pragma unroll
            for (int j = 0; j < 4; j++) {
                c1[i][j] += aa1[i]*bb1[j];
                c2[i][j] += aa2[i]*bb2[j];
            }
        }
        __syncthreads();
    }
    #pragma unroll
    for (int i = 0; i < 4; i++) {
        int row = bi*32 + ty*4 + i;
        int col = bj*32 + tx*4;
        float4 a1 = *(const float4*)&g_A1[row*Ndim + col];
        float4 a2 = *(const float4*)&g_A2[row*Ndim + col];
        float s[4] = {a1.x+a2.x, a1.y+a2.y, a1.z+a2.z, a1.w+a2.w};
        #pragma unroll
        for (int j = 0; j < 4; j++) {
            g_Ms2[row*Ndim + col + j] = splitf(OMA*s[j]);
            g_Ms2[(160+row)*Ndim + col + j] =
                splitf(ALPHA*OMA*s[j] + OMA*OMA*(c1[i][j]+c2[i][j]));
        }
    }
}

// ============================================================
// K3: folded weights (split)
// ============================================================
__global__ void k_wcprep(const float* __restrict__ We, const float* __restrict__ Wp) {
    int idx = blockIdx.x*256 + threadIdx.x;
    if (idx >= 64*96) return;
    int o = idx / 96, k = idx % 96;
    const float* W = (o < 32) ? We : Wp;
    int oo = o & 31;
    float v;
    if (k < 32) v = 2.f*W[oo*96 + k] + 2.f*ALPHA*(W[oo*96 + k + 32] + W[oo*96 + k + 64]);
    else        v = W[oo*96 + k];
    g_Wc2[o*96 + k] = splitf(v);
}

// ============================================================
// K3b: split copy of x
// ============================================================
__global__ void k_xsplit(const float* __restrict__ x) {
    size_t i4 = ((size_t)blockIdx.x*256 + threadIdx.x)*4;
    float4 v = *(const float4*)&x[i4];
    float2 o0 = splitf(v.x), o1 = splitf(v.y), o2 = splitf(v.z), o3 = splitf(v.w);
    *(float4*)&g_x2[i4]   = make_float4(o0.x, o0.y, o1.x, o1.y);
    *(float4*)&g_x2[i4+2] = make_float4(o2.x, o2.y, o3.x, o3.y);
}

// ============================================================
// K4: batched TF32 split GEMM on pre-split data.
// CTA = 160(M) x 80(N), 320 thr, warps 5(M)x2(N), warp tile 32x40.
// K = 160 in 10 chunks of 16, cp.async double-buffered, 2 CTAs/SM.
// TA=false: A [M][K]; TA=true: A [K][M].  SOUT: split output.
// ============================================================
template<bool TA>
struct TG {
    static const int AS = TA ? 16*164 : 160*20;   // float2 units
    static const int BS = 16*84;
    static const int STG = AS + BS;
    static const int SMEM = STG*2*8;
};

template<bool TA, bool SOUT>
__global__ void __launch_bounds__(320, 2) k_tgemm5(
    const float2* __restrict__ A, long sA, int lda,
    const float2* __restrict__ B, long sB, int ldb,
    void* __restrict__ C, long sC, int ldc)
{
    extern __shared__ float2 sm2[];
    const int AS = TG<TA>::AS, STG = TG<TA>::STG;
    uint32_t sb = (uint32_t)__cvta_generic_to_shared(sm2);

    int bc = blockIdx.x;
    int n0 = blockIdx.y * 80;
    int m0 = blockIdx.z * 160;
    const float2* Ab = A + (size_t)bc*sA;
    const float2* Bb = B + (size_t)bc*sB;

    int tid = threadIdx.x, lane = tid & 31, wid = tid >> 5;
    int wmi = wid % 5, wni = wid / 5;
    int g = lane >> 2, t = lane & 3;

    float acc[2][5][4] = {};

    auto stage = [&](int kt, int st) {
        uint32_t base = sb + (uint32_t)(st*STG)*8;
        if (TA) {
            #pragma unroll
            for (int i = 0; i < 4; i++) {
                int s = tid + i*320;
                int k = s / 80, mc = (s % 80)*2;
                cp16(base + (uint32_t)(k*164 + mc)*8, &Ab[(size_t)(kt+k)*lda + m0 + mc]);
            }
        } else {
            #pragma unroll
            for (int i = 0; i < 4; i++) {
                int s = tid + i*320;
                int m = s >> 3, kc = (s & 7)*2;
                cp16(base + (uint32_t)(m*20 + kc)*8, &Ab[(size_t)(m0+m)*lda + kt + kc]);
            }
        }
        uint32_t bbase = base + (uint32_t)AS*8;
        #pragma unroll
        for (int i = 0; i < 2; i++) {
            int s = tid + i*320;
            int k = s / 40, nc2 = (s % 40)*2;
            cp16(bbase + (uint32_t)(k*84 + nc2)*8, &Bb[(size_t)(kt+k)*ldb + n0 + nc2]);
        }
        CP_COMMIT();
    };

    stage(0, 0);
    for (int it = 0; it < 10; it++) {
        if (it + 1 < 10) { stage((it+1)*16, (it+1)&1); cp_wait<1>(); }
        else             { cp_wait<0>(); }
        __syncthreads();
        const float2* As = sm2 + (it&1)*STG;
        const float2* Bs = As + AS;
        #pragma unroll
        for (int kk = 0; kk < 16; kk += 8) {
            uint32_t Ah[2][4], Al[2][4];
            #pragma unroll
            for (int mt = 0; mt < 2; mt++) {
                int mr = wmi*32 + mt*16 + g;
                float2 v0, v1, v2, v3;
                if (TA) {
                    v0 = As[(kk+t)*164 + mr];   v1 = As[(kk+t)*164 + mr + 8];
                    v2 = As[(kk+t+4)*164 + mr]; v3 = As[(kk+t+4)*164 + mr + 8];
                } else {
                    v0 = As[mr*20 + kk + t];       v1 = As[(mr+8)*20 + kk + t];
                    v2 = As[mr*20 + kk + t + 4];   v3 = As[(mr+8)*20 + kk + t + 4];
                }
                Ah[mt][0] = __float_as_uint(v0.x); Al[mt][0] = __float_as_uint(v0.y);
                Ah[mt][1] = __float_as_uint(v1.x); Al[mt][1] = __float_as_uint(v1.y);
                Ah[mt][2] = __float_as_uint(v2.x); Al[mt][2] = __float_as_uint(v2.y);
                Ah[mt][3] = __float_as_uint(v3.x); Al[mt][3] = __float_as_uint(v3.y);
            }
            #pragma unroll
            for (int nt = 0; nt < 5; nt++) {
                int nc = wni*40 + nt*8 + g;
                float2 b0 = Bs[(kk+t)*84 + nc];
                float2 b1 = Bs[(kk+t+4)*84 + nc];
                uint32_t bh[2] = {__float_as_uint(b0.x), __float_as_uint(b1.x)};
                uint32_t bl[2] = {__float_as_uint(b0.y), __float_as_uint(b1.y)};
                #pragma unroll
                for (int mt = 0; mt < 2; mt++) {
                    mma8(acc[mt][nt], Ah[mt], bh);
                    mma8(acc[mt][nt], Ah[mt], bl);
                    mma8(acc[mt][nt], Al[mt], bh);
                }
            }
        }
        __syncthreads();
    }
    #pragma unroll
    for (int mt = 0; mt < 2; mt++) {
        int r0 = m0 + wmi*32 + mt*16 + g;
        #pragma unroll
        for (int nt = 0; nt < 5; nt++) {
            int c0 = n0 + wni*40 + nt*8 + 2*t;
            if (SOUT) {
                float2* C2 = (float2*)C + (size_t)bc*sC;
                float2 s0 = splitf(acc[mt][nt][0]), s1 = splitf(acc[mt][nt][1]);
                float2 s2 = splitf(acc[mt][nt][2]), s3 = splitf(acc[mt][nt][3]);
                *(float4*)&C2[(size_t)r0*ldc + c0]     = make_float4(s0.x,s0.y,s1.x,s1.y);
                *(float4*)&C2[(size_t)(r0+8)*ldc + c0] = make_float4(s2.x,s2.y,s3.x,s3.y);
            } else {
                float* Cf = (float*)C + (size_t)bc*sC;
                *(float2*)&Cf[(size_t)r0*ldc + c0] =
                    make_float2(acc[mt][nt][0], acc[mt][nt][1]);
                *(float2*)&Cf[(size_t)(r0+8)*ldc + c0] =
                    make_float2(acc[mt][nt][2], acc[mt][nt][3]);
            }
        }
    }
}

// ============================================================
// K5: channel mix on pre-split data. CTA = 64 x 160, K=96 (6 chunks of 16).
// ============================================================
#define MIX_AS (64*20)
#define MIX_BS (16*164)
#define MIX_STG (MIX_AS + MIX_BS)
#define MIX_SMEM (MIX_STG*2*8)

__global__ void __launch_bounds__(320, 2) k_mix3(
    const float* __restrict__ be, const float* __restrict__ bp)
{
    extern __shared__ float2 sm2[];
    uint32_t sb = (uint32_t)__cvta_generic_to_shared(sm2);
    int b  = blockIdx.y;
    int p0 = blockIdx.x * 160;
    int tid = threadIdx.x, lane = tid & 31, wid = tid >> 5;
    int wmi = wid & 1, wni = wid >> 1;
    int g = lane >> 2, t = lane & 3;

    float acc[2][4][4] = {};

    auto stage = [&](int ktc, int st) {
        uint32_t base = sb + (uint32_t)(st*MIX_STG)*8;
        #pragma unroll
        for (int i = 0; i < 2; i++) {
            int s = tid + i*320;
            if (s < 512) {
                int m = s >> 3, kc = (s & 7)*2;
                cp16(base + (uint32_t)(m*20 + kc)*8, &g_Wc2[m*96 + ktc + kc]);
            }
        }
        uint32_t bbase = base + (uint32_t)MIX_AS*8;
        #pragma unroll
        for (int i = 0; i < 4; i++) {
            int s = tid + i*320;
            int k = s / 80, mc = (s % 80)*2;
            int kg = ktc + k;
            int c = kg & 31;
            const float2* src;
            if (kg < 32)      src = g_x2 + ((size_t)b*32 + c)*NL;
            else if (kg < 64) src = g_y2 + ((size_t)b*32 + c)*(2*NL);
            else              src = g_y2 + ((size_t)b*32 + c)*(2*NL) + NL;
            cp16(bbase + (uint32_t)(k*164 + mc)*8, &src[p0 + mc]);
        }
        CP_COMMIT();
    };

    stage(0, 0);
    for (int it = 0; it < 6; it++) {
        if (it + 1 < 6) { stage((it+1)*16, (it+1)&1); cp_wait<1>(); }
        else            { cp_wait<0>(); }
        __syncthreads();
        const float2* As = sm2 + (it&1)*MIX_STG;
        const float2* Bs = As + MIX_AS;
        #pragma unroll
        for (int kk = 0; kk < 16; kk += 8) {
            uint32_t Ah[2][4], Al[2][4];
            #pragma unroll
            for (int mt = 0; mt < 2; mt++) {
                int mr = wmi*32 + mt*16 + g;
                float2 v0 = As[mr*20 + kk + t],     v1 = As[(mr+8)*20 + kk + t];
                float2 v2 = As[mr*20 + kk + t + 4], v3 = As[(mr+8)*20 + kk + t + 4];
                Ah[mt][0] = __float_as_uint(v0.x); Al[mt][0] = __float_as_uint(v0.y);
                Ah[mt][1] = __float_as_uint(v1.x); Al[mt][1] = __float_as_uint(v1.y);
                Ah[mt][2] = __float_as_uint(v2.x); Al[mt][2] = __float_as_uint(v2.y);
                Ah[mt][3] = __float_as_uint(v3.x); Al[mt][3] = __float_as_uint(v3.y);
            }
            #pragma unroll
            for (int nt = 0; nt < 4; nt++) {
                int nc = wni*32 + nt*8 + g;
                float2 b0 = Bs[(kk+t)*164 + nc];
                float2 b1 = Bs[(kk+t+4)*164 + nc];
                uint32_t bh[2] = {__float_as_uint(b0.x), __float_as_uint(b1.x)};
                uint32_t bl[2] = {__float_as_uint(b0.y), __float_as_uint(b1.y)};
                #pragma unroll
                for (int mt = 0; mt < 2; mt++) {
                    mma8(acc[mt][nt], Ah[mt], bh);
                    mma8(acc[mt][nt], Ah[mt], bl);
                    mma8(acc[mt][nt], Al[mt], bh);
                }
            }
        }
        __syncthreads();
    }
    #pragma unroll
    for (int mt = 0; mt < 2; mt++) {
        #pragma unroll
        for (int rr = 0; rr < 2; rr++) {
            int o = wmi*32 + mt*16 + g + rr*8;
            float bias = 2.f * ((o < 32) ? be[o] : bp[o-32]);
            int oo = o & 31;
            size_t base = ((size_t)b*32 + oo)*NL + p0;
            #pragma unroll
            for (int nt = 0; nt < 4; nt++) {
                int c0 = wni*32 + nt*8 + 2*t;
                float u0 = acc[mt][nt][rr*2+0] + bias;
                float u1 = acc[mt][nt][rr*2+1] + bias;
                if (o < 32) {
                    float2 s0 = splitf(u0), s1 = splitf(u1);
                    *(float4*)&g_e2[base + c0] = make_float4(s0.x,s0.y,s1.x,s1.y);
                } else {
                    *(float2*)&g_pool[base + c0] = make_float2(u0, u1);
                }
            }
        }
    }
}

// ============================================================
// K6: softmax over node axis, smem-cached, split output
// ============================================================
#define SMAX_SMEM (160*161*4)
__global__ void k_softmax2() {
    extern __shared__ float sp[];
    int bc = blockIdx.x;
    int l = threadIdx.x;
    const float* p = g_pool + (size_t)bc*NL;
    for (int n = 0; n < Ndim; n++)
        sp[n*161 + l] = p[n*Ndim + l];
    __syncthreads();
    float m = -3.4e38f, d = 0.f;
    #pragma unroll 4
    for (int n = 0; n < Ndim; n++) {
        float v = sp[n*161 + l];
        float m2 = fmaxf(m, v);
        d = d * __expf(m - m2) + __expf(v - m2);
        m = m2;
    }
    float inv = 1.f / d;
    float2* s2 = g_s2 + (size_t)bc*NL;
    #pragma unroll 4
    for (int n = 0; n < Ndim; n++)
        s2[n*Ndim + l] = splitf(__expf(sp[n*161 + l] - m) * inv);
}

// ============================================================
extern "C" void kernel_launch(void* const* d_in, const int* in_sizes, int n_in,
                              void* d_out, int out_size) {
    const float* x  = (const float*)d_in[0];
    const float* a  = (const float*)d_in[1];
    const float* We = (const float*)d_in[2];
    const float* be = (const float*)d_in[3];
    const float* Wp = (const float*)d_in[4];
    const float* bp = (const float*)d_in[5];
    float* out  = (float*)d_out;
    float* xnew = out;
    float* anew = out + (size_t)BC*NL;

    void *p_s2, *p_e2, *p_t2, *p_Ms2, *p_y2, *p_a2, *p_x2;
    cudaGetSymbolAddress(&p_s2,  g_s2);
    cudaGetSymbolAddress(&p_e2,  g_e2);
    cudaGetSymbolAddress(&p_t2,  g_t2);
    cudaGetSymbolAddress(&p_Ms2, g_Ms2);
    cudaGetSymbolAddress(&p_y2,  g_y2);
    cudaGetSymbolAddress(&p_a2,  g_a2);
    cudaGetSymbolAddress(&p_x2,  g_x2);

    cudaFuncSetAttribute((const void*)k_tgemm5<false,true>,  cudaFuncAttributeMaxDynamicSharedMemorySize, TG<false>::SMEM);
    cudaFuncSetAttribute((const void*)k_tgemm5<false,false>, cudaFuncAttributeMaxDynamicSharedMemorySize, TG<false>::SMEM);
    cudaFuncSetAttribute((const void*)k_tgemm5<true,false>,  cudaFuncAttributeMaxDynamicSharedMemorySize, TG<true>::SMEM);
    cudaFuncSetAttribute((const void*)k_mix3, cudaFuncAttributeMaxDynamicSharedMemorySize, MIX_SMEM);
    cudaFuncSetAttribute((const void*)k_softmax2, cudaFuncAttributeMaxDynamicSharedMemorySize, SMAX_SMEM);

    k_norm_adj<<<Ndim, Ndim>>>(a);
    k_prep<<<dim3(5, 5), 64>>>();
    k_wcprep<<<(64*96 + 255)/256, 256>>>(We, Wp);
    k_xsplit<<<(int)(((size_t)BC*NL)/1024), 256>>>(x);

    // ystack = Mstack @ x : split in, split out
    k_tgemm5<false,true><<<dim3(BC, 2, 2), 320, TG<false>::SMEM>>>(
        (const float2*)p_Ms2, 0, Ndim, (const float2*)p_x2, NL, Ndim,
        p_y2, 2*NL, Ndim);

    // channel mix -> embed(split), pool(raw)
    k_mix3<<<dim3(NL/160, Bdim), 320, MIX_SMEM>>>(be, bp);

    k_softmax2<<<BC, Ndim, SMAX_SMEM>>>();

    // x_new = s^T @ embed (TA), raw out
    k_tgemm5<true,false><<<dim3(BC, 2, 1), 320, TG<true>::SMEM>>>(
        (const float2*)p_s2, NL, Ndim, (const float2*)p_e2, NL, Ndim,
        xnew, NL, Ndim);

    // t = s @ a (B shared), split out
    k_tgemm5<false,true><<<dim3(BC, 2, 1), 320, TG<false>::SMEM>>>(
        (const float2*)p_s2, NL, Ndim, (const float2*)p_a2, 0, Ndim,
        (void*)p_t2, NL, Ndim);

    // a_new = t @ s, raw out
    k_tgemm5<false,false><<<dim3(BC, 2, 1), 320, TG<false>::SMEM>>>(
        (const float2*)p_t2, NL, Ndim, (const float2*)p_s2, NL, Ndim,
        anew, NL, Ndim);
}

// round 8
// speedup vs baseline: 1.8819x; 1.8819x over previous
#include <cuda_runtime.h>
#include <cuda_bf16.h>
#include <cstdint>

#define Bdim 32
#define Ndim 160
#define NL 25600           // 160*160
#define BC 1024            // 32*32
#define ALPHA 0.05f
#define OMA 0.95f

// ---- scratch (__device__ globals). GEMM operands stored as TWO bf16 planes
// (hi = bf16(v), lo = bf16(v - hi)) in the SAME layout as the fp32 original.
// Total bytes identical to fp32. ----
__device__ __align__(16) float g_A1[Ndim*Ndim];
__device__ __align__(16) float g_A2[Ndim*Ndim];
__device__ __align__(16) __nv_bfloat16 g_Msh[2*Ndim*Ndim], g_Msl[2*Ndim*Ndim];
__device__ __align__(16) __nv_bfloat16 g_ah [Ndim*Ndim],   g_al [Ndim*Ndim];
__device__ __align__(16) __nv_bfloat16 g_Wch[64*96],       g_Wcl[64*96];
__device__ __align__(16) __nv_bfloat16 g_xh[(size_t)BC*NL],   g_xl[(size_t)BC*NL];
__device__ __align__(16) __nv_bfloat16 g_yh[(size_t)BC*2*NL], g_yl[(size_t)BC*2*NL];
__device__ __align__(16) __nv_bfloat16 g_eh[(size_t)BC*NL],   g_el[(size_t)BC*NL];
__device__ __align__(16) float g_pool[(size_t)BC*NL];
__device__ __align__(16) __nv_bfloat16 g_sh[(size_t)BC*NL],   g_sl[(size_t)BC*NL];
__device__ __align__(16) __nv_bfloat16 g_th[(size_t)BC*NL],   g_tl[(size_t)BC*NL];

// ---------- helpers ----------
__device__ __forceinline__ uint32_t packbf(float v0, float v1) {
    // word: low 16 = bf16(v0), high 16 = bf16(v1)  (memory order v0, v1)
    uint32_t w; asm("cvt.rn.bf16x2.f32 %0, %1, %2;" : "=r"(w) : "f"(v1), "f"(v0));
    return w;
}
__device__ __forceinline__ void split_pair(float v0, float v1, uint32_t& wh, uint32_t& wl) {
    wh = packbf(v0, v1);
    float u0 = __uint_as_float(wh << 16);
    float u1 = __uint_as_float(wh & 0xFFFF0000u);
    wl = packbf(v0 - u0, v1 - u1);
}
__device__ __forceinline__ void splitb(float v, __nv_bfloat16* h, __nv_bfloat16* l) {
    __nv_bfloat16 hh = __float2bfloat16(v);
    *h = hh;
    *l = __float2bfloat16(v - __bfloat162float(hh));
}
__device__ __forceinline__ void mmabf(float* c, const uint32_t* a, const uint32_t* b) {
    asm volatile(
        "mma.sync.aligned.m16n8k16.row.col.f32.bf16.bf16.f32 "
        "{%0,%1,%2,%3}, {%4,%5,%6,%7}, {%8,%9}, {%0,%1,%2,%3};"
        : "+f"(c[0]), "+f"(c[1]), "+f"(c[2]), "+f"(c[3])
        : "r"(a[0]), "r"(a[1]), "r"(a[2]), "r"(a[3]), "r"(b[0]), "r"(b[1]));
}
__device__ __forceinline__ void ldsm4(uint32_t* r, uint32_t a) {
    asm volatile("ldmatrix.sync.aligned.m8n8.x4.shared.b16 {%0,%1,%2,%3}, [%4];"
        : "=r"(r[0]), "=r"(r[1]), "=r"(r[2]), "=r"(r[3]) : "r"(a));
}
__device__ __forceinline__ void ldsm4t(uint32_t* r, uint32_t a) {
    asm volatile("ldmatrix.sync.aligned.m8n8.x4.trans.shared.b16 {%0,%1,%2,%3}, [%4];"
        : "=r"(r[0]), "=r"(r[1]), "=r"(r[2]), "=r"(r[3]) : "r"(a));
}
__device__ __forceinline__ void ldsm2t(uint32_t* r, uint32_t a) {
    asm volatile("ldmatrix.sync.aligned.m8n8.x2.trans.shared.b16 {%0,%1}, [%2];"
        : "=r"(r[0]), "=r"(r[1]) : "r"(a));
}
__device__ __forceinline__ void cp16(uint32_t saddr, const void* gptr) {
    asm volatile("cp.async.cg.shared.global [%0], [%1], 16;" :: "r"(saddr), "l"(gptr));
}
#define CP_COMMIT() asm volatile("cp.async.commit_group;")
template<int N> __device__ __forceinline__ void cp_wait() {
    asm volatile("cp.async.wait_group %0;" :: "n"(N));
}

// ============================================================
// K1: row-normalized (a+I), (a^T+I) fp32; split copy of raw a
// ============================================================
__global__ void k_norm_adj(const float* __restrict__ a) {
    int v = blockIdx.x;
    int t = threadIdx.x;
    __shared__ float s1[Ndim], s2[Ndim];
    __shared__ float r1, r2;
    float av = a[v*Ndim + t];
    float aw = a[t*Ndim + v];
    s1[t] = av; s2[t] = aw;
    __syncthreads();
    if (t == 0) {
        float x1 = 0.f, x2 = 0.f;
        for (int i = 0; i < Ndim; i++) { x1 += s1[i]; x2 += s2[i]; }
        r1 = x1 + 1.f; r2 = x2 + 1.f;
    }
    __syncthreads();
    float diag = (t == v) ? 1.f : 0.f;
    g_A1[v*Ndim + t] = (av + diag) / r1;
    g_A2[v*Ndim + t] = (aw + diag) / r2;
    splitb(av, &g_ah[v*Ndim + t], &g_al[v*Ndim + t]);
}

// ============================================================
// K2: Mstack fp32 GEMM, split outputs into Ms planes
// ============================================================
__global__ void k_prep() {
    __shared__ float As1[32][36], As2[32][36], Bs1[32][36], Bs2[32][36];
    int tid = threadIdx.x;
    int tx = tid & 7, ty = tid >> 3;
    int bi = blockIdx.y, bj = blockIdx.x;
    float c1[4][4] = {}, c2[4][4] = {};
    for (int kt = 0; kt < 5; kt++) {
        #pragma unroll
        for (int it = 0; it < 4; it++) {
            int g = tid + it*64;
            int m = g >> 3, k4 = g & 7;
            float4 v1 = *(const float4*)&g_A1[(bi*32+m)*Ndim + kt*32 + k4*4];
            float4 v2 = *(const float4*)&g_A2[(bi*32+m)*Ndim + kt*32 + k4*4];
            As1[k4*4+0][m] = v1.x; As1[k4*4+1][m] = v1.y;
            As1[k4*4+2][m] = v1.z; As1[k4*4+3][m] = v1.w;
            As2[k4*4+0][m] = v2.x; As2[k4*4+1][m] = v2.y;
            As2[k4*4+2][m] = v2.z; As2[k4*4+3][m] = v2.w;
            int r = g >> 3, c4 = g & 7;
            *(float4*)&Bs1[r][c4*4] = *(const float4*)&g_A1[(kt*32+r)*Ndim + bj*32 + c4*4];
            *(float4*)&Bs2[r][c4*4] = *(const float4*)&g_A2[(kt*32+r)*Ndim + bj*32 + c4*4];
        }
        __syncthreads();
        #pragma unroll
        for (int k = 0; k < 32; k++) {
            float4 a1 = *(const float4*)&As1[k][ty*4];
            float4 a2 = *(const float4*)&As2[k][ty*4];
            float4 b1 = *(const float4*)&Bs1[k][tx*4];
            float4 b2 = *(const float4*)&Bs2[k][tx*4];
            float aa1[4] = {a1.x,a1.y,a1.z,a1.w}, aa2[4] = {a2.x,a2.y,a2.z,a2.w};
            float bb1[4] = {b1.x,b1.y,b1.z,b1.w}, bb2[4] = {b2.x,b2.y,b2.z,b2.w};
            #pragma unroll
            for (int i = 0; i < 4; i++)
            #pragma unroll
            for (int j = 0; j < 4; j++) {
                c1[i][j] += aa1[i]*bb1[j];
                c2[i][j] += aa2[i]*bb2[j];
            }
        }
        __syncthreads();
    }
    #pragma unroll
    for (int i = 0; i < 4; i++) {
        int row = bi*32 + ty*4 + i;
        int col = bj*32 + tx*4;
        float4 a1 = *(const float4*)&g_A1[row*Ndim + col];
        float4 a2 = *(const float4*)&g_A2[row*Ndim + col];
        float sv[4] = {a1.x+a2.x, a1.y+a2.y, a1.z+a2.z, a1.w+a2.w};
        #pragma unroll
        for (int j = 0; j < 4; j++) {
            splitb(OMA*sv[j], &g_Msh[row*Ndim + col + j], &g_Msl[row*Ndim + col + j]);
            splitb(ALPHA*OMA*sv[j] + OMA*OMA*(c1[i][j]+c2[i][j]),
                   &g_Msh[(160+row)*Ndim + col + j], &g_Msl[(160+row)*Ndim + col + j]);
        }
    }
}

// ============================================================
// K3: folded weights (split planes)
// ============================================================
__global__ void k_wcprep(const float* __restrict__ We, const float* __restrict__ Wp) {
    int idx = blockIdx.x*256 + threadIdx.x;
    if (idx >= 64*96) return;
    int o = idx / 96, k = idx % 96;
    const float* W = (o < 32) ? We : Wp;
    int oo = o & 31;
    float v;
    if (k < 32) v = 2.f*W[oo*96 + k] + 2.f*ALPHA*(W[oo*96 + k + 32] + W[oo*96 + k + 64]);
    else        v = W[oo*96 + k];
    splitb(v, &g_Wch[idx], &g_Wcl[idx]);
}

// ============================================================
// K3b: split x into planes (same layout, same total bytes)
// ============================================================
__global__ void k_xsplit(const float* __restrict__ x) {
    size_t i4 = ((size_t)blockIdx.x*256 + threadIdx.x)*4;
    float4 v = *(const float4*)&x[i4];
    uint32_t h01, l01, h23, l23;
    split_pair(v.x, v.y, h01, l01);
    split_pair(v.z, v.w, h23, l23);
    *(uint2*)&g_xh[i4] = make_uint2(h01, h23);
    *(uint2*)&g_xl[i4] = make_uint2(l01, l23);
}

// ============================================================
// K4: batched bf16x2-planar GEMM via mma.m16n8k16 + ldmatrix.
// CTA = 160(M) x 80(N), 320 thr, warps 5(M)x2(N), warp tile 32x40.
// K = 160 in 5 chunks of 32 (2 x k16), cp.async double-buffered, 2 CTAs/SM.
// TA=false: A gmem [M][K] -> smem [m][40]; TA=true: A gmem [K][M] -> smem [k][168] (+ldsm.trans).
// B gmem [K][N] -> smem [k][88], fragments via ldsm.trans.
// SOUT: split (planar bf16) output, else raw fp32 output.
// ============================================================
template<bool TA>
struct TGB {
    static const int AS = TA ? 32*168 : 160*40;  // elems per A plane
    static const int BS = 32*88;
    static const int STGE = 2*AS + 2*BS;         // elems per stage (4 planes)
    static const int SMEM = STGE*2*2;            // bytes (2 stages, 2B/elem)
};

template<bool TA, bool SOUT>
__global__ void __launch_bounds__(320, 2) k_bgemm_bf(
    const __nv_bfloat16* __restrict__ Ah, const __nv_bfloat16* __restrict__ Al,
    long sA, int lda,
    const __nv_bfloat16* __restrict__ Bh, const __nv_bfloat16* __restrict__ Bl,
    long sB, int ldb,
    void* __restrict__ Coh, void* __restrict__ Col, long sC, int ldc)
{
    extern __shared__ __nv_bfloat16 smb[];
    const int AS = TGB<TA>::AS, STGE = TGB<TA>::STGE;
    uint32_t sb = (uint32_t)__cvta_generic_to_shared(smb);

    int bc = blockIdx.x;
    int n0 = blockIdx.y * 80;
    int m0 = blockIdx.z * 160;
    const __nv_bfloat16* Ahb = Ah + (size_t)bc*sA;
    const __nv_bfloat16* Alb = Al + (size_t)bc*sA;
    const __nv_bfloat16* Bhb = Bh + (size_t)bc*sB;
    const __nv_bfloat16* Blb = Bl + (size_t)bc*sB;

    int tid = threadIdx.x, lane = tid & 31, wid = tid >> 5;
    int wmi = wid % 5, wni = wid / 5;         // 5(M) x 2(N)
    int m0w = wmi*32, n0w = wni*40;
    int g = lane >> 2, t = lane & 3;

    float acc[2][5][4] = {};

    auto stage = [&](int kt, int st) {
        uint32_t base = sb + (uint32_t)(st*STGE)*2;
        if (TA) {
            // A [k32][m160] per plane: 640 cp16/plane, 1280 both
            #pragma unroll
            for (int i = 0; i < 4; i++) {
                int s = tid + i*320;
                int pl = s >= 640; int ss = s - pl*640;
                int k = ss/20, mc = (ss%20)*8;
                const __nv_bfloat16* src = (pl ? Alb : Ahb) + (size_t)(kt+k)*lda + m0 + mc;
                cp16(base + (uint32_t)(pl*AS + k*168 + mc)*2, src);
            }
        } else {
            // A [m160][k32]: 640 cp16/plane
            #pragma unroll
            for (int i = 0; i < 4; i++) {
                int s = tid + i*320;
                int pl = s >= 640; int ss = s - pl*640;
                int m = ss >> 2, kc = (ss & 3)*8;
                const __nv_bfloat16* src = (pl ? Alb : Ahb) + (size_t)(m0+m)*lda + kt + kc;
                cp16(base + (uint32_t)(pl*AS + m*40 + kc)*2, src);
            }
        }
        // B [k32][n80]: 320 cp16/plane, 640 both
        #pragma unroll
        for (int i = 0; i < 2; i++) {
            int s = tid + i*320;
            int pl = s >= 320; int ss = s - pl*320;
            int k = ss/10, nc = (ss%10)*8;
            const __nv_bfloat16* src = (pl ? Blb : Bhb) + (size_t)(kt+k)*ldb + n0 + nc;
            cp16(base + (uint32_t)(2*AS + pl*TGB<TA>::BS + k*88 + nc)*2, src);
        }
        CP_COMMIT();
    };

    stage(0, 0);
    #pragma unroll
    for (int it = 0; it < 5; it++) {
        if (it + 1 < 5) { stage((it+1)*32, (it+1)&1); cp_wait<1>(); }
        else            { cp_wait<0>(); }
        __syncthreads();
        uint32_t sAh = sb + (uint32_t)((it&1)*STGE)*2;
        uint32_t sAl = sAh + (uint32_t)AS*2;
        uint32_t sBh = sAh + (uint32_t)(2*AS)*2;
        uint32_t sBl = sBh + (uint32_t)TGB<TA>::BS*2;
        #pragma unroll
        for (int kk = 0; kk < 32; kk += 16) {
            uint32_t Afh[2][4], Afl[2][4];
            #pragma unroll
            for (int mt = 0; mt < 2; mt++) {
                uint32_t off;
                if (TA) {
                    off = (uint32_t)(((kk + (lane&7) + ((lane>>4)<<3))*168
                                      + m0w + mt*16 + (lane&8)) << 1);
                    ldsm4t(Afh[mt], sAh + off);
                    ldsm4t(Afl[mt], sAl + off);
                } else {
                    off = (uint32_t)(((m0w + mt*16 + (lane&15))*40
                                      + kk + ((lane>>4)<<3)) << 1);
                    ldsm4(Afh[mt], sAh + off);
                    ldsm4(Afl[mt], sAl + off);
                }
            }
            uint32_t Bfh[5][2], Bfl[5][2];
            int rB = kk + (lane&7) + (lane&8);
            #pragma unroll
            for (int ntp = 0; ntp < 2; ntp++) {
                uint32_t off = (uint32_t)((rB*88 + n0w + ntp*16 + ((lane>>4)<<3)) << 1);
                uint32_t rh[4], rl[4];
                ldsm4t(rh, sBh + off);
                ldsm4t(rl, sBl + off);
                Bfh[2*ntp][0]=rh[0]; Bfh[2*ntp][1]=rh[1]; Bfh[2*ntp+1][0]=rh[2]; Bfh[2*ntp+1][1]=rh[3];
                Bfl[2*ntp][0]=rl[0]; Bfl[2*ntp][1]=rl[1]; Bfl[2*ntp+1][0]=rl[2]; Bfl[2*ntp+1][1]=rl[3];
            }
            {
                uint32_t off = (uint32_t)((rB*88 + n0w + 32) << 1);
                ldsm2t(Bfh[4], sBh + off);
                ldsm2t(Bfl[4], sBl + off);
            }
            #pragma unroll
            for (int nt = 0; nt < 5; nt++)
            #pragma unroll
            for (int mt = 0; mt < 2; mt++) {
                mmabf(acc[mt][nt], Afh[mt], Bfh[nt]);
                mmabf(acc[mt][nt], Afh[mt], Bfl[nt]);
                mmabf(acc[mt][nt], Afl[mt], Bfh[nt]);
            }
        }
        __syncthreads();
    }
    // ---- epilogue ----
    #pragma unroll
    for (int mt = 0; mt < 2; mt++) {
        int r0 = m0 + m0w + mt*16 + g;
        #pragma unroll
        for (int nt = 0; nt < 5; nt++) {
            int c0 = n0 + n0w + nt*8 + 2*t;
            if (SOUT) {
                __nv_bfloat16* Ch = (__nv_bfloat16*)Coh + (size_t)bc*sC;
                __nv_bfloat16* Cl = (__nv_bfloat16*)Col + (size_t)bc*sC;
                uint32_t wh, wl;
                split_pair(acc[mt][nt][0], acc[mt][nt][1], wh, wl);
                *(uint32_t*)&Ch[(size_t)r0*ldc + c0] = wh;
                *(uint32_t*)&Cl[(size_t)r0*ldc + c0] = wl;
                split_pair(acc[mt][nt][2], acc[mt][nt][3], wh, wl);
                *(uint32_t*)&Ch[(size_t)(r0+8)*ldc + c0] = wh;
                *(uint32_t*)&Cl[(size_t)(r0+8)*ldc + c0] = wl;
            } else {
                float* Cf = (float*)Coh + (size_t)bc*sC;
                *(float2*)&Cf[(size_t)r0*ldc + c0] =
                    make_float2(acc[mt][nt][0], acc[mt][nt][1]);
                *(float2*)&Cf[(size_t)(r0+8)*ldc + c0] =
                    make_float2(acc[mt][nt][2], acc[mt][nt][3]);
            }
        }
    }
}

// ============================================================
// K5: channel mix, bf16 planar. CTA = 64(M) x 160(N), K=96 (3 chunks of 32).
// warps 2(M)x5(N), warp tile 32x32 (nt=4). embed->split planes, pool->fp32.
// ============================================================
#define MIXB_AS (64*40)
#define MIXB_BS (32*168)
#define MIXB_STGE (2*MIXB_AS + 2*MIXB_BS)
#define MIXB_SMEM (MIXB_STGE*2*2)

__global__ void __launch_bounds__(320, 2) k_mix_bf(
    const float* __restrict__ be, const float* __restrict__ bp)
{
    extern __shared__ __nv_bfloat16 smb[];
    uint32_t sb = (uint32_t)__cvta_generic_to_shared(smb);
    int b  = blockIdx.y;
    int p0 = blockIdx.x * 160;
    int tid = threadIdx.x, lane = tid & 31, wid = tid >> 5;
    int wmi = wid & 1, wni = wid >> 1;
    int m0w = wmi*32, n0w = wni*32;
    int g = lane >> 2, t = lane & 3;

    float acc[2][4][4] = {};

    auto stage = [&](int ktc, int st) {
        uint32_t base = sb + (uint32_t)(st*MIXB_STGE)*2;
        // A (Wc) [64][32] per plane: 256 cp16/plane, 512 both
        #pragma unroll
        for (int i = 0; i < 2; i++) {
            int s = tid + i*320;
            if (s < 512) {
                int pl = s >= 256; int ss = s & 255;
                int m = ss >> 2, kc = (ss & 3)*8;
                const __nv_bfloat16* src = (pl ? g_Wcl : g_Wch) + m*96 + ktc + kc;
                cp16(base + (uint32_t)(pl*MIXB_AS + m*40 + kc)*2, src);
            }
        }
        // B [k32][160]: 640 cp16/plane, 1280 both
        #pragma unroll
        for (int i = 0; i < 4; i++) {
            int s = tid + i*320;
            int pl = s >= 640; int ss = s - pl*640;
            int k = ss/20, mc = (ss%20)*8;
            int kg = ktc + k;
            int c = kg & 31;
            const __nv_bfloat16* src;
            if (pl) {
                if (kg < 32)      src = g_xl + ((size_t)b*32 + c)*NL;
                else if (kg < 64) src = g_yl + ((size_t)b*32 + c)*(2*NL);
                else              src = g_yl + ((size_t)b*32 + c)*(2*NL) + NL;
            } else {
                if (kg < 32)      src = g_xh + ((size_t)b*32 + c)*NL;
                else if (kg < 64) src = g_yh + ((size_t)b*32 + c)*(2*NL);
                else              src = g_yh + ((size_t)b*32 + c)*(2*NL) + NL;
            }
            cp16(base + (uint32_t)(2*MIXB_AS + pl*MIXB_BS + k*168 + mc)*2, src + p0 + mc);
        }
        CP_COMMIT();
    };

    stage(0, 0);
    #pragma unroll
    for (int it = 0; it < 3; it++) {
        if (it + 1 < 3) { stage((it+1)*32, (it+1)&1); cp_wait<1>(); }
        else            { cp_wait<0>(); }
        __syncthreads();
        uint32_t sAh = sb + (uint32_t)((it&1)*MIXB_STGE)*2;
        uint32_t sAl = sAh + (uint32_t)MIXB_AS*2;
        uint32_t sBh = sAh + (uint32_t)(2*MIXB_AS)*2;
        uint32_t sBl = sBh + (uint32_t)MIXB_BS*2;
        #pragma unroll
        for (int kk = 0; kk < 32; kk += 16) {
            uint32_t Afh[2][4], Afl[2][4];
            #pragma unroll
            for (int mt = 0; mt < 2; mt++) {
                uint32_t off = (uint32_t)(((m0w + mt*16 + (lane&15))*40
                                           + kk + ((lane>>4)<<3)) << 1);
                ldsm4(Afh[mt], sAh + off);
                ldsm4(Afl[mt], sAl + off);
            }
            uint32_t Bfh[4][2], Bfl[4][2];
            int rB = kk + (lane&7) + (lane&8);
            #pragma unroll
            for (int ntp = 0; ntp < 2; ntp++) {
                uint32_t off = (uint32_t)((rB*168 + n0w + ntp*16 + ((lane>>4)<<3)) << 1);
                uint32_t rh[4], rl[4];
                ldsm4t(rh, sBh + off);
                ldsm4t(rl, sBl + off);
                Bfh[2*ntp][0]=rh[0]; Bfh[2*ntp][1]=rh[1]; Bfh[2*ntp+1][0]=rh[2]; Bfh[2*ntp+1][1]=rh[3];
                Bfl[2*ntp][0]=rl[0]; Bfl[2*ntp][1]=rl[1]; Bfl[2*ntp+1][0]=rl[2]; Bfl[2*ntp+1][1]=rl[3];
            }
            #pragma unroll
            for (int nt = 0; nt < 4; nt++)
            #pragma unroll
            for (int mt = 0; mt < 2; mt++) {
                mmabf(acc[mt][nt], Afh[mt], Bfh[nt]);
                mmabf(acc[mt][nt], Afh[mt], Bfl[nt]);
                mmabf(acc[mt][nt], Afl[mt], Bfh[nt]);
            }
        }
        __syncthreads();
    }
    #pragma unroll
    for (int mt = 0; mt < 2; mt++) {
        #pragma unroll
        for (int rr = 0; rr < 2; rr++) {
            int o = m0w + mt*16 + g + rr*8;
            float bias = 2.f * ((o < 32) ? be[o] : bp[o-32]);
            int oo = o & 31;
            size_t base = ((size_t)b*32 + oo)*NL + p0;
            #pragma unroll
            for (int nt = 0; nt < 4; nt++) {
                int c0 = n0w + nt*8 + 2*t;
                float u0 = acc[mt][nt][rr*2+0] + bias;
                float u1 = acc[mt][nt][rr*2+1] + bias;
                if (o < 32) {
                    uint32_t wh, wl;
                    split_pair(u0, u1, wh, wl);
                    *(uint32_t*)&g_eh[base + c0] = wh;
                    *(uint32_t*)&g_el[base + c0] = wl;
                } else {
                    *(float2*)&g_pool[base + c0] = make_float2(u0, u1);
                }
            }
        }
    }
}

// ============================================================
// K6: softmax over node axis; split bf16 planar output
// ============================================================
#define SMAX_SMEM (160*161*4)
__global__ void k_softmax3() {
    extern __shared__ float sp[];
    int bc = blockIdx.x;
    int l = threadIdx.x;
    const float* p = g_pool + (size_t)bc*NL;
    for (int n = 0; n < Ndim; n++)
        sp[n*161 + l] = p[n*Ndim + l];
    __syncthreads();
    float m = -3.4e38f, d = 0.f;
    #pragma unroll 4
    for (int n = 0; n < Ndim; n++) {
        float v = sp[n*161 + l];
        float m2 = fmaxf(m, v);
        d = d * __expf(m - m2) + __expf(v - m2);
        m = m2;
    }
    float inv = 1.f / d;
    __nv_bfloat16* sh = g_sh + (size_t)bc*NL;
    __nv_bfloat16* sl = g_sl + (size_t)bc*NL;
    #pragma unroll 4
    for (int n = 0; n < Ndim; n++) {
        float v = __expf(sp[n*161 + l] - m) * inv;
        splitb(v, &sh[n*Ndim + l], &sl[n*Ndim + l]);
    }
}

// ============================================================
extern "C" void kernel_launch(void* const* d_in, const int* in_sizes, int n_in,
                              void* d_out, int out_size) {
    const float* x  = (const float*)d_in[0];
    const float* a  = (const float*)d_in[1];
    const float* We = (const float*)d_in[2];
    const float* be = (const float*)d_in[3];
    const float* Wp = (const float*)d_in[4];
    const float* bp = (const float*)d_in[5];
    float* out  = (float*)d_out;
    float* xnew = out;
    float* anew = out + (size_t)BC*NL;

    void *pMsh, *pMsl, *pxh, *pxl, *pyh, *pyl, *peh, *pel, *psh, *psl,
         *pth, *ptl, *pah, *pal;
    cudaGetSymbolAddress(&pMsh, g_Msh); cudaGetSymbolAddress(&pMsl, g_Msl);
    cudaGetSymbolAddress(&pxh,  g_xh);  cudaGetSymbolAddress(&pxl,  g_xl);
    cudaGetSymbolAddress(&pyh,  g_yh);  cudaGetSymbolAddress(&pyl,  g_yl);
    cudaGetSymbolAddress(&peh,  g_eh);  cudaGetSymbolAddress(&pel,  g_el);
    cudaGetSymbolAddress(&psh,  g_sh);  cudaGetSymbolAddress(&psl,  g_sl);
    cudaGetSymbolAddress(&pth,  g_th);  cudaGetSymbolAddress(&ptl,  g_tl);
    cudaGetSymbolAddress(&pah,  g_ah);  cudaGetSymbolAddress(&pal,  g_al);

    cudaFuncSetAttribute((const void*)k_bgemm_bf<false,true>,
        cudaFuncAttributeMaxDynamicSharedMemorySize, TGB<false>::SMEM);
    cudaFuncSetAttribute((const void*)k_bgemm_bf<false,false>,
        cudaFuncAttributeMaxDynamicSharedMemorySize, TGB<false>::SMEM);
    cudaFuncSetAttribute((const void*)k_bgemm_bf<true,false>,
        cudaFuncAttributeMaxDynamicSharedMemorySize, TGB<true>::SMEM);
    cudaFuncSetAttribute((const void*)k_mix_bf,
        cudaFuncAttributeMaxDynamicSharedMemorySize, MIXB_SMEM);
    cudaFuncSetAttribute((const void*)k_softmax3,
        cudaFuncAttributeMaxDynamicSharedMemorySize, SMAX_SMEM);

    k_norm_adj<<<Ndim, Ndim>>>(a);
    k_prep<<<dim3(5, 5), 64>>>();
    k_wcprep<<<(64*96 + 255)/256, 256>>>(We, Wp);
    k_xsplit<<<(int)(((size_t)BC*NL)/1024), 256>>>(x);

    // ystack = Ms @ x : A shared (sA=0), B = x planes, C = y planes (split)
    k_bgemm_bf<false,true><<<dim3(BC, 2, 2), 320, TGB<false>::SMEM>>>(
        (const __nv_bfloat16*)pMsh, (const __nv_bfloat16*)pMsl, 0, Ndim,
        (const __nv_bfloat16*)pxh,  (const __nv_bfloat16*)pxl,  NL, Ndim,
        pyh, pyl, 2*NL, Ndim);

    // channel mix -> embed (split planes), pool (fp32)
    k_mix_bf<<<dim3(NL/160, Bdim), 320, MIXB_SMEM>>>(be, bp);

    k_softmax3<<<BC, Ndim, SMAX_SMEM>>>();

    // x_new = s^T @ embed : A = s planes [k=n][m=l] (TA), raw fp32 out
    k_bgemm_bf<true,false><<<dim3(BC, 2, 1), 320, TGB<true>::SMEM>>>(
        (const __nv_bfloat16*)psh, (const __nv_bfloat16*)psl, NL, Ndim,
        (const __nv_bfloat16*)peh, (const __nv_bfloat16*)pel, NL, Ndim,
        xnew, nullptr, NL, Ndim);

    // t = s @ a : B shared (sB=0), split out
    k_bgemm_bf<false,true><<<dim3(BC, 2, 1), 320, TGB<false>::SMEM>>>(
        (const __nv_bfloat16*)psh, (const __nv_bfloat16*)psl, NL, Ndim,
        (const __nv_bfloat16*)pah, (const __nv_bfloat16*)pal, 0, Ndim,
        pth, ptl, NL, Ndim);

    // a_new = t @ s : raw fp32 out
    k_bgemm_bf<false,false><<<dim3(BC, 2, 1), 320, TGB<false>::SMEM>>>(
        (const __nv_bfloat16*)pth, (const __nv_bfloat16*)ptl, NL, Ndim,
        (const __nv_bfloat16*)psh, (const __nv_bfloat16*)psl, NL, Ndim,
        anew, nullptr, NL, Ndim);
}

// round 9
// speedup vs baseline: 1.9349x; 1.0281x over previous
#include <cuda_runtime.h>
#include <cuda_bf16.h>
#include <cstdint>

#define Bdim 32
#define Ndim 160
#define NL 25600           // 160*160
#define BC 1024            // 32*32
#define ALPHA 0.05f
#define OMA 0.95f

// ---- scratch (__device__ globals). GEMM operands stored as TWO bf16 planes
// (hi = bf16(v), lo = bf16(v - hi)); byte-neutral vs fp32. ----
__device__ __align__(16) float g_A1[Ndim*Ndim];
__device__ __align__(16) float g_A2[Ndim*Ndim];
__device__ __align__(16) __nv_bfloat16 g_Msh[2*Ndim*Ndim], g_Msl[2*Ndim*Ndim];
__device__ __align__(16) __nv_bfloat16 g_ah [Ndim*Ndim],   g_al [Ndim*Ndim];
__device__ __align__(16) __nv_bfloat16 g_Wch[64*96],       g_Wcl[64*96];
__device__ __align__(16) __nv_bfloat16 g_xh[(size_t)BC*NL],   g_xl[(size_t)BC*NL];
__device__ __align__(16) __nv_bfloat16 g_yh[(size_t)BC*2*NL], g_yl[(size_t)BC*2*NL];
__device__ __align__(16) __nv_bfloat16 g_eh[(size_t)BC*NL],   g_el[(size_t)BC*NL];
__device__ __align__(16) float g_pool[(size_t)BC*NL];
__device__ __align__(16) __nv_bfloat16 g_sh[(size_t)BC*NL],   g_sl[(size_t)BC*NL];

// ---------- helpers ----------
__device__ __forceinline__ uint32_t packbf(float v0, float v1) {
    uint32_t w; asm("cvt.rn.bf16x2.f32 %0, %1, %2;" : "=r"(w) : "f"(v1), "f"(v0));
    return w;
}
__device__ __forceinline__ void split_pair(float v0, float v1, uint32_t& wh, uint32_t& wl) {
    wh = packbf(v0, v1);
    float u0 = __uint_as_float(wh << 16);
    float u1 = __uint_as_float(wh & 0xFFFF0000u);
    wl = packbf(v0 - u0, v1 - u1);
}
__device__ __forceinline__ void splitb(float v, __nv_bfloat16* h, __nv_bfloat16* l) {
    __nv_bfloat16 hh = __float2bfloat16(v);
    *h = hh;
    *l = __float2bfloat16(v - __bfloat162float(hh));
}
__device__ __forceinline__ void mmabf(float* c, const uint32_t* a, const uint32_t* b) {
    asm volatile(
        "mma.sync.aligned.m16n8k16.row.col.f32.bf16.bf16.f32 "
        "{%0,%1,%2,%3}, {%4,%5,%6,%7}, {%8,%9}, {%0,%1,%2,%3};"
        : "+f"(c[0]), "+f"(c[1]), "+f"(c[2]), "+f"(c[3])
        : "r"(a[0]), "r"(a[1]), "r"(a[2]), "r"(a[3]), "r"(b[0]), "r"(b[1]));
}
__device__ __forceinline__ void ldsm4(uint32_t* r, uint32_t a) {
    asm volatile("ldmatrix.sync.aligned.m8n8.x4.shared.b16 {%0,%1,%2,%3}, [%4];"
        : "=r"(r[0]), "=r"(r[1]), "=r"(r[2]), "=r"(r[3]) : "r"(a));
}
__device__ __forceinline__ void ldsm4t(uint32_t* r, uint32_t a) {
    asm volatile("ldmatrix.sync.aligned.m8n8.x4.trans.shared.b16 {%0,%1,%2,%3}, [%4];"
        : "=r"(r[0]), "=r"(r[1]), "=r"(r[2]), "=r"(r[3]) : "r"(a));
}
__device__ __forceinline__ void ldsm2t(uint32_t* r, uint32_t a) {
    asm volatile("ldmatrix.sync.aligned.m8n8.x2.trans.shared.b16 {%0,%1}, [%2];"
        : "=r"(r[0]), "=r"(r[1]) : "r"(a));
}
__device__ __forceinline__ void cp16(uint32_t saddr, const void* gptr) {
    asm volatile("cp.async.cg.shared.global [%0], [%1], 16;" :: "r"(saddr), "l"(gptr));
}
#define CP_COMMIT() asm volatile("cp.async.commit_group;")
template<int N> __device__ __forceinline__ void cp_wait() {
    asm volatile("cp.async.wait_group %0;" :: "n"(N));
}

// ============================================================
// K1: row-normalized (a+I), (a^T+I) fp32; split copy of raw a
// ============================================================
__global__ void k_norm_adj(const float* __restrict__ a) {
    int v = blockIdx.x;
    int t = threadIdx.x;
    __shared__ float s1[Ndim], s2[Ndim];
    __shared__ float r1, r2;
    float av = a[v*Ndim + t];
    float aw = a[t*Ndim + v];
    s1[t] = av; s2[t] = aw;
    __syncthreads();
    if (t == 0) {
        float x1 = 0.f, x2 = 0.f;
        for (int i = 0; i < Ndim; i++) { x1 += s1[i]; x2 += s2[i]; }
        r1 = x1 + 1.f; r2 = x2 + 1.f;
    }
    __syncthreads();
    float diag = (t == v) ? 1.f : 0.f;
    g_A1[v*Ndim + t] = (av + diag) / r1;
    g_A2[v*Ndim + t] = (aw + diag) / r2;
    splitb(av, &g_ah[v*Ndim + t], &g_al[v*Ndim + t]);
}

// ============================================================
// K2: Mstack fp32 GEMM, split outputs into Ms planes
// ============================================================
__global__ void k_prep() {
    __shared__ float As1[32][36], As2[32][36], Bs1[32][36], Bs2[32][36];
    int tid = threadIdx.x;
    int tx = tid & 7, ty = tid >> 3;
    int bi = blockIdx.y, bj = blockIdx.x;
    float c1[4][4] = {}, c2[4][4] = {};
    for (int kt = 0; kt < 5; kt++) {
        #pragma unroll
        for (int it = 0; it < 4; it++) {
            int g = tid + it*64;
            int m = g >> 3, k4 = g & 7;
            float4 v1 = *(const float4*)&g_A1[(bi*32+m)*Ndim + kt*32 + k4*4];
            float4 v2 = *(const float4*)&g_A2[(bi*32+m)*Ndim + kt*32 + k4*4];
            As1[k4*4+0][m] = v1.x; As1[k4*4+1][m] = v1.y;
            As1[k4*4+2][m] = v1.z; As1[k4*4+3][m] = v1.w;
            As2[k4*4+0][m] = v2.x; As2[k4*4+1][m] = v2.y;
            As2[k4*4+2][m] = v2.z; As2[k4*4+3][m] = v2.w;
            int r = g >> 3, c4 = g & 7;
            *(float4*)&Bs1[r][c4*4] = *(const float4*)&g_A1[(kt*32+r)*Ndim + bj*32 + c4*4];
            *(float4*)&Bs2[r][c4*4] = *(const float4*)&g_A2[(kt*32+r)*Ndim + bj*32 + c4*4];
        }
        __syncthreads();
        #pragma unroll
        for (int k = 0; k < 32; k++) {
            float4 a1 = *(const float4*)&As1[k][ty*4];
            float4 a2 = *(const float4*)&As2[k][ty*4];
            float4 b1 = *(const float4*)&Bs1[k][tx*4];
            float4 b2 = *(const float4*)&Bs2[k][tx*4];
            float aa1[4] = {a1.x,a1.y,a1.z,a1.w}, aa2[4] = {a2.x,a2.y,a2.z,a2.w};
            float bb1[4] = {b1.x,b1.y,b1.z,b1.w}, bb2[4] = {b2.x,b2.y,b2.z,b2.w};
            #pragma unroll
            for (int i = 0; i < 4; i++)
            #pragma unroll
            for (int j = 0; j < 4; j++) {
                c1[i][j] += aa1[i]*bb1[j];
                c2[i][j] += aa2[i]*bb2[j];
            }
        }
        __syncthreads();
    }
    #pragma unroll
    for (int i = 0; i < 4; i++) {
        int row = bi*32 + ty*4 + i;
        int col = bj*32 + tx*4;
        float4 a1 = *(const float4*)&g_A1[row*Ndim + col];
        float4 a2 = *(const float4*)&g_A2[row*Ndim + col];
        float sv[4] = {a1.x+a2.x, a1.y+a2.y, a1.z+a2.z, a1.w+a2.w};
        #pragma unroll
        for (int j = 0; j < 4; j++) {
            splitb(OMA*sv[j], &g_Msh[row*Ndim + col + j], &g_Msl[row*Ndim + col + j]);
            splitb(ALPHA*OMA*sv[j] + OMA*OMA*(c1[i][j]+c2[i][j]),
                   &g_Msh[(160+row)*Ndim + col + j], &g_Msl[(160+row)*Ndim + col + j]);
        }
    }
}

// ============================================================
// K3: folded weights (split planes)
// ============================================================
__global__ void k_wcprep(const float* __restrict__ We, const float* __restrict__ Wp) {
    int idx = blockIdx.x*256 + threadIdx.x;
    if (idx >= 64*96) return;
    int o = idx / 96, k = idx % 96;
    const float* W = (o < 32) ? We : Wp;
    int oo = o & 31;
    float v;
    if (k < 32) v = 2.f*W[oo*96 + k] + 2.f*ALPHA*(W[oo*96 + k + 32] + W[oo*96 + k + 64]);
    else        v = W[oo*96 + k];
    splitb(v, &g_Wch[idx], &g_Wcl[idx]);
}

// ============================================================
// K3b: split x into planes
// ============================================================
__global__ void k_xsplit(const float* __restrict__ x) {
    size_t i4 = ((size_t)blockIdx.x*256 + threadIdx.x)*4;
    float4 v = *(const float4*)&x[i4];
    uint32_t h01, l01, h23, l23;
    split_pair(v.x, v.y, h01, l01);
    split_pair(v.z, v.w, h23, l23);
    *(uint2*)&g_xh[i4] = make_uint2(h01, h23);
    *(uint2*)&g_xl[i4] = make_uint2(l01, l23);
}

// ============================================================
// K4: batched bf16-planar GEMM (y-stage only). Same as R8.
// CTA = 160(M) x 80(N), 320 thr, warps 5(M)x2(N). Split output.
// ============================================================
struct TGB {
    static const int AS = 160*40;
    static const int BS = 32*88;
    static const int STGE = 2*AS + 2*BS;
    static const int SMEM = STGE*2*2;
};

__global__ void __launch_bounds__(320, 2) k_bgemm_bf(
    const __nv_bfloat16* __restrict__ Ah, const __nv_bfloat16* __restrict__ Al,
    long sA, int lda,
    const __nv_bfloat16* __restrict__ Bh, const __nv_bfloat16* __restrict__ Bl,
    long sB, int ldb,
    __nv_bfloat16* __restrict__ Coh, __nv_bfloat16* __restrict__ Col,
    long sC, int ldc)
{
    extern __shared__ __nv_bfloat16 smb[];
    const int AS = TGB::AS, STGE = TGB::STGE;
    uint32_t sb = (uint32_t)__cvta_generic_to_shared(smb);

    int bc = blockIdx.x;
    int n0 = blockIdx.y * 80;
    int m0 = blockIdx.z * 160;
    const __nv_bfloat16* Ahb = Ah + (size_t)bc*sA;
    const __nv_bfloat16* Alb = Al + (size_t)bc*sA;
    const __nv_bfloat16* Bhb = Bh + (size_t)bc*sB;
    const __nv_bfloat16* Blb = Bl + (size_t)bc*sB;

    int tid = threadIdx.x, lane = tid & 31, wid = tid >> 5;
    int wmi = wid % 5, wni = wid / 5;
    int m0w = wmi*32, n0w = wni*40;
    int g = lane >> 2, t = lane & 3;

    float acc[2][5][4] = {};

    auto stage = [&](int kt, int st) {
        uint32_t base = sb + (uint32_t)(st*STGE)*2;
        #pragma unroll
        for (int i = 0; i < 4; i++) {
            int s = tid + i*320;
            int pl = s >= 640; int ss = s - pl*640;
            int m = ss >> 2, kc = (ss & 3)*8;
            const __nv_bfloat16* src = (pl ? Alb : Ahb) + (size_t)(m0+m)*lda + kt + kc;
            cp16(base + (uint32_t)(pl*AS + m*40 + kc)*2, src);
        }
        #pragma unroll
        for (int i = 0; i < 2; i++) {
            int s = tid + i*320;
            int pl = s >= 320; int ss = s - pl*320;
            int k = ss/10, nc = (ss%10)*8;
            const __nv_bfloat16* src = (pl ? Blb : Bhb) + (size_t)(kt+k)*ldb + n0 + nc;
            cp16(base + (uint32_t)(2*AS + pl*TGB::BS + k*88 + nc)*2, src);
        }
        CP_COMMIT();
    };

    stage(0, 0);
    #pragma unroll
    for (int it = 0; it < 5; it++) {
        if (it + 1 < 5) { stage((it+1)*32, (it+1)&1); cp_wait<1>(); }
        else            { cp_wait<0>(); }
        __syncthreads();
        uint32_t sAh = sb + (uint32_t)((it&1)*STGE)*2;
        uint32_t sAl = sAh + (uint32_t)AS*2;
        uint32_t sBh = sAh + (uint32_t)(2*AS)*2;
        uint32_t sBl = sBh + (uint32_t)TGB::BS*2;
        #pragma unroll
        for (int kk = 0; kk < 32; kk += 16) {
            uint32_t Afh[2][4], Afl[2][4];
            #pragma unroll
            for (int mt = 0; mt < 2; mt++) {
                uint32_t off = (uint32_t)(((m0w + mt*16 + (lane&15))*40
                                           + kk + ((lane>>4)<<3)) << 1);
                ldsm4(Afh[mt], sAh + off);
                ldsm4(Afl[mt], sAl + off);
            }
            uint32_t Bfh[5][2], Bfl[5][2];
            int rB = kk + (lane&7) + (lane&8);
            #pragma unroll
            for (int ntp = 0; ntp < 2; ntp++) {
                uint32_t off = (uint32_t)((rB*88 + n0w + ntp*16 + ((lane>>4)<<3)) << 1);
                uint32_t rh[4], rl[4];
                ldsm4t(rh, sBh + off);
                ldsm4t(rl, sBl + off);
                Bfh[2*ntp][0]=rh[0]; Bfh[2*ntp][1]=rh[1]; Bfh[2*ntp+1][0]=rh[2]; Bfh[2*ntp+1][1]=rh[3];
                Bfl[2*ntp][0]=rl[0]; Bfl[2*ntp][1]=rl[1]; Bfl[2*ntp+1][0]=rl[2]; Bfl[2*ntp+1][1]=rl[3];
            }
            {
                uint32_t off = (uint32_t)((rB*88 + n0w + 32) << 1);
                ldsm2t(Bfh[4], sBh + off);
                ldsm2t(Bfl[4], sBl + off);
            }
            #pragma unroll
            for (int nt = 0; nt < 5; nt++)
            #pragma unroll
            for (int mt = 0; mt < 2; mt++) {
                mmabf(acc[mt][nt], Afh[mt], Bfh[nt]);
                mmabf(acc[mt][nt], Afh[mt], Bfl[nt]);
                mmabf(acc[mt][nt], Afl[mt], Bfh[nt]);
            }
        }
        __syncthreads();
    }
    #pragma unroll
    for (int mt = 0; mt < 2; mt++) {
        int r0 = m0 + m0w + mt*16 + g;
        #pragma unroll
        for (int nt = 0; nt < 5; nt++) {
            int c0 = n0 + n0w + nt*8 + 2*t;
            __nv_bfloat16* Ch = Coh + (size_t)bc*sC;
            __nv_bfloat16* Cl = Col + (size_t)bc*sC;
            uint32_t wh, wl;
            split_pair(acc[mt][nt][0], acc[mt][nt][1], wh, wl);
            *(uint32_t*)&Ch[(size_t)r0*ldc + c0] = wh;
            *(uint32_t*)&Cl[(size_t)r0*ldc + c0] = wl;
            split_pair(acc[mt][nt][2], acc[mt][nt][3], wh, wl);
            *(uint32_t*)&Ch[(size_t)(r0+8)*ldc + c0] = wh;
            *(uint32_t*)&Cl[(size_t)(r0+8)*ldc + c0] = wl;
        }
    }
}

// ============================================================
// K5: channel mix, bf16 planar (unchanged from R8).
// ============================================================
#define MIXB_AS (64*40)
#define MIXB_BS (32*168)
#define MIXB_STGE (2*MIXB_AS + 2*MIXB_BS)
#define MIXB_SMEM (MIXB_STGE*2*2)

__global__ void __launch_bounds__(320, 2) k_mix_bf(
    const float* __restrict__ be, const float* __restrict__ bp)
{
    extern __shared__ __nv_bfloat16 smb[];
    uint32_t sb = (uint32_t)__cvta_generic_to_shared(smb);
    int b  = blockIdx.y;
    int p0 = blockIdx.x * 160;
    int tid = threadIdx.x, lane = tid & 31, wid = tid >> 5;
    int wmi = wid & 1, wni = wid >> 1;
    int m0w = wmi*32, n0w = wni*32;
    int g = lane >> 2, t = lane & 3;

    float acc[2][4][4] = {};

    auto stage = [&](int ktc, int st) {
        uint32_t base = sb + (uint32_t)(st*MIXB_STGE)*2;
        #pragma unroll
        for (int i = 0; i < 2; i++) {
            int s = tid + i*320;
            if (s < 512) {
                int pl = s >= 256; int ss = s & 255;
                int m = ss >> 2, kc = (ss & 3)*8;
                const __nv_bfloat16* src = (pl ? g_Wcl : g_Wch) + m*96 + ktc + kc;
                cp16(base + (uint32_t)(pl*MIXB_AS + m*40 + kc)*2, src);
            }
        }
        #pragma unroll
        for (int i = 0; i < 4; i++) {
            int s = tid + i*320;
            int pl = s >= 640; int ss = s - pl*640;
            int k = ss/20, mc = (ss%20)*8;
            int kg = ktc + k;
            int c = kg & 31;
            const __nv_bfloat16* src;
            if (pl) {
                if (kg < 32)      src = g_xl + ((size_t)b*32 + c)*NL;
                else if (kg < 64) src = g_yl + ((size_t)b*32 + c)*(2*NL);
                else              src = g_yl + ((size_t)b*32 + c)*(2*NL) + NL;
            } else {
                if (kg < 32)      src = g_xh + ((size_t)b*32 + c)*NL;
                else if (kg < 64) src = g_yh + ((size_t)b*32 + c)*(2*NL);
                else              src = g_yh + ((size_t)b*32 + c)*(2*NL) + NL;
            }
            cp16(base + (uint32_t)(2*MIXB_AS + pl*MIXB_BS + k*168 + mc)*2, src + p0 + mc);
        }
        CP_COMMIT();
    };

    stage(0, 0);
    #pragma unroll
    for (int it = 0; it < 3; it++) {
        if (it + 1 < 3) { stage((it+1)*32, (it+1)&1); cp_wait<1>(); }
        else            { cp_wait<0>(); }
        __syncthreads();
        uint32_t sAh = sb + (uint32_t)((it&1)*MIXB_STGE)*2;
        uint32_t sAl = sAh + (uint32_t)MIXB_AS*2;
        uint32_t sBh = sAh + (uint32_t)(2*MIXB_AS)*2;
        uint32_t sBl = sBh + (uint32_t)MIXB_BS*2;
        #pragma unroll
        for (int kk = 0; kk < 32; kk += 16) {
            uint32_t Afh[2][4], Afl[2][4];
            #pragma unroll
            for (int mt = 0; mt < 2; mt++) {
                uint32_t off = (uint32_t)(((m0w + mt*16 + (lane&15))*40
                                           + kk + ((lane>>4)<<3)) << 1);
                ldsm4(Afh[mt], sAh + off);
                ldsm4(Afl[mt], sAl + off);
            }
            uint32_t Bfh[4][2], Bfl[4][2];
            int rB = kk + (lane&7) + (lane&8);
            #pragma unroll
            for (int ntp = 0; ntp < 2; ntp++) {
                uint32_t off = (uint32_t)((rB*168 + n0w + ntp*16 + ((lane>>4)<<3)) << 1);
                uint32_t rh[4], rl[4];
                ldsm4t(rh, sBh + off);
                ldsm4t(rl, sBl + off);
                Bfh[2*ntp][0]=rh[0]; Bfh[2*ntp][1]=rh[1]; Bfh[2*ntp+1][0]=rh[2]; Bfh[2*ntp+1][1]=rh[3];
                Bfl[2*ntp][0]=rl[0]; Bfl[2*ntp][1]=rl[1]; Bfl[2*ntp+1][0]=rl[2]; Bfl[2*ntp+1][1]=rl[3];
            }
            #pragma unroll
            for (int nt = 0; nt < 4; nt++)
            #pragma unroll
            for (int mt = 0; mt < 2; mt++) {
                mmabf(acc[mt][nt], Afh[mt], Bfh[nt]);
                mmabf(acc[mt][nt], Afh[mt], Bfl[nt]);
                mmabf(acc[mt][nt], Afl[mt], Bfh[nt]);
            }
        }
        __syncthreads();
    }
    #pragma unroll
    for (int mt = 0; mt < 2; mt++) {
        #pragma unroll
        for (int rr = 0; rr < 2; rr++) {
            int o = m0w + mt*16 + g + rr*8;
            float bias = 2.f * ((o < 32) ? be[o] : bp[o-32]);
            int oo = o & 31;
            size_t base = ((size_t)b*32 + oo)*NL + p0;
            #pragma unroll
            for (int nt = 0; nt < 4; nt++) {
                int c0 = n0w + nt*8 + 2*t;
                float u0 = acc[mt][nt][rr*2+0] + bias;
                float u1 = acc[mt][nt][rr*2+1] + bias;
                if (o < 32) {
                    uint32_t wh, wl;
                    split_pair(u0, u1, wh, wl);
                    *(uint32_t*)&g_eh[base + c0] = wh;
                    *(uint32_t*)&g_el[base + c0] = wl;
                } else {
                    *(float2*)&g_pool[base + c0] = make_float2(u0, u1);
                }
            }
        }
    }
}

// ============================================================
// K6: softmax over node axis; split bf16 planar output
// ============================================================
#define SMAX_SMEM (160*161*4)
__global__ void k_softmax3() {
    extern __shared__ float sp[];
    int bc = blockIdx.x;
    int l = threadIdx.x;
    const float* p = g_pool + (size_t)bc*NL;
    for (int n = 0; n < Ndim; n++)
        sp[n*161 + l] = p[n*Ndim + l];
    __syncthreads();
    float m = -3.4e38f, d = 0.f;
    #pragma unroll 4
    for (int n = 0; n < Ndim; n++) {
        float v = sp[n*161 + l];
        float m2 = fmaxf(m, v);
        d = d * __expf(m - m2) + __expf(v - m2);
        m = m2;
    }
    float inv = 1.f / d;
    __nv_bfloat16* sh = g_sh + (size_t)bc*NL;
    __nv_bfloat16* sl = g_sl + (size_t)bc*NL;
    #pragma unroll 4
    for (int n = 0; n < Ndim; n++) {
        float v = __expf(sp[n*161 + l] - m) * inv;
        splitb(v, &sh[n*Ndim + l], &sl[n*Ndim + l]);
    }
}

// ============================================================
// K7: FUSED epilogue. One CTA per (bc, half): s resident in smem.
//   phase0: x_new[l][l'] = sum_n s[n][l] e[n][l']   (A = s^T, B = e streamed)
//   phase1: t[n][m]      = sum_l s[n][l] a[l][m]    (A = s,   B = a streamed, t -> smem)
//   phase2: a_new[n][l'] = sum_m t[n][m] s[m][l']   (A = t,   B = s, all smem)
// 320 thr, warps 5(M: 16 rows) x 2(N: 80 cols), M=80 rows per CTA half.
// smem (bf16 elems): s_h[160][168], s_l, t_h[80][168], t_l, 3-stage ring of
// [32][168] x 2 planes. Total 225,792 B.
// ============================================================
#define EPI_SL   26880
#define EPI_TH   53760
#define EPI_TL   67200
#define EPI_STG  80640
#define EPI_STG_PL 5376
#define EPI_STG_ST 10752
#define EPI_SMEM (112896*2)

__device__ __forceinline__ void frag_mma_row(
    float (&acc)[10][4], const uint32_t* Ah, const uint32_t* Al,
    uint32_t sBh, uint32_t sBl, int rB, int ldb, int n0w, int lane)
{
    #pragma unroll
    for (int ntp = 0; ntp < 5; ntp++) {
        uint32_t off = (uint32_t)((rB*ldb + n0w + ntp*16 + ((lane>>4)<<3)) << 1);
        uint32_t rh[4], rl[4];
        ldsm4t(rh, sBh + off);
        ldsm4t(rl, sBl + off);
        uint32_t bh0[2] = {rh[0], rh[1]}, bh1[2] = {rh[2], rh[3]};
        uint32_t bl0[2] = {rl[0], rl[1]}, bl1[2] = {rl[2], rl[3]};
        mmabf(acc[2*ntp],   Ah, bh0);
        mmabf(acc[2*ntp],   Ah, bl0);
        mmabf(acc[2*ntp],   Al, bh0);
        mmabf(acc[2*ntp+1], Ah, bh1);
        mmabf(acc[2*ntp+1], Ah, bl1);
        mmabf(acc[2*ntp+1], Al, bh1);
    }
}

__global__ void __launch_bounds__(320, 1) k_epi(
    float* __restrict__ xnew, float* __restrict__ anew)
{
    extern __shared__ __nv_bfloat16 smb[];
    uint32_t sb = (uint32_t)__cvta_generic_to_shared(smb);
    int bc = blockIdx.x;
    int h  = blockIdx.y;                  // 0/1: which 80-row half
    int tid = threadIdx.x, lane = tid & 31, wid = tid >> 5;
    int wmi = wid % 5, wni = wid / 5;
    int g = lane >> 2, t4 = lane & 3;
    int m0 = h*80 + wmi*16;               // absolute M base for this warp
    int n0w = wni*80;

    const __nv_bfloat16* sh_g = g_sh + (size_t)bc*NL;
    const __nv_bfloat16* sl_g = g_sl + (size_t)bc*NL;
    const __nv_bfloat16* eh_g = g_eh + (size_t)bc*NL;
    const __nv_bfloat16* el_g = g_el + (size_t)bc*NL;

    // ---- prologue: async-load both s planes (commit group 0) ----
    #pragma unroll
    for (int i = 0; i < 20; i++) {
        int s = tid + i*320;              // 0..6399
        int pl = s >= 3200; int ss = s - pl*3200;
        int r = ss/20, c8 = (ss%20)*8;
        const __nv_bfloat16* src = (pl ? sl_g : sh_g) + r*160 + c8;
        cp16(sb + (uint32_t)((pl ? EPI_SL : 0) + r*168 + c8)*2, src);
    }
    CP_COMMIT();

    auto stage = [&](const __nv_bfloat16* bh, const __nv_bfloat16* bl,
                     int ch, int slot) {
        uint32_t base = sb + (uint32_t)(EPI_STG + slot*EPI_STG_ST)*2;
        #pragma unroll
        for (int i = 0; i < 4; i++) {
            int s = tid + i*320;
            int pl = s >= 640; int ss = s - pl*640;
            int r = ss/20, c8 = (ss%20)*8;
            const __nv_bfloat16* src = (pl ? bl : bh) + (ch*32 + r)*160 + c8;
            cp16(base + (uint32_t)(pl*EPI_STG_PL + r*168 + c8)*2, src);
        }
        CP_COMMIT();
    };

    float acc[10][4];

    // ================= phase 0: x_new = s^T @ e =================
    #pragma unroll
    for (int i = 0; i < 10; i++)
        acc[i][0] = acc[i][1] = acc[i][2] = acc[i][3] = 0.f;
    stage(eh_g, el_g, 0, 0);
    stage(eh_g, el_g, 1, 1);
    for (int ch = 0; ch < 5; ch++) {
        if (ch + 2 < 5) stage(eh_g, el_g, ch+2, (ch+2)%3); else CP_COMMIT();
        cp_wait<2>();
        __syncthreads();
        uint32_t stb  = sb + (uint32_t)(EPI_STG + (ch%3)*EPI_STG_ST)*2;
        uint32_t stbl = stb + (uint32_t)EPI_STG_PL*2;
        #pragma unroll
        for (int kk = 0; kk < 32; kk += 16) {
            int kg = ch*32 + kk;
            uint32_t Ah[4], Al[4];
            uint32_t offA = (uint32_t)(((kg + (lane&7) + ((lane>>4)<<3))*168
                                        + m0 + (lane&8)) << 1);
            ldsm4t(Ah, sb + offA);
            ldsm4t(Al, sb + (uint32_t)(EPI_SL*2) + offA);
            int rB = kk + (lane&7) + (lane&8);
            frag_mma_row(acc, Ah, Al, stb, stbl, rB, 168, n0w, lane);
        }
        __syncthreads();
    }
    {
        float* X = xnew + (size_t)bc*NL;
        int r0 = m0 + g;
        #pragma unroll
        for (int nt = 0; nt < 10; nt++) {
            int c0 = n0w + nt*8 + 2*t4;
            *(float2*)&X[(size_t)r0*160 + c0]     = make_float2(acc[nt][0], acc[nt][1]);
            *(float2*)&X[(size_t)(r0+8)*160 + c0] = make_float2(acc[nt][2], acc[nt][3]);
        }
    }

    // ================= phase 1: t = s @ a (t -> smem) =================
    #pragma unroll
    for (int i = 0; i < 10; i++)
        acc[i][0] = acc[i][1] = acc[i][2] = acc[i][3] = 0.f;
    stage(g_ah, g_al, 0, 0);
    stage(g_ah, g_al, 1, 1);
    for (int ch = 0; ch < 5; ch++) {
        if (ch + 2 < 5) stage(g_ah, g_al, ch+2, (ch+2)%3); else CP_COMMIT();
        cp_wait<2>();
        __syncthreads();
        uint32_t stb  = sb + (uint32_t)(EPI_STG + (ch%3)*EPI_STG_ST)*2;
        uint32_t stbl = stb + (uint32_t)EPI_STG_PL*2;
        #pragma unroll
        for (int kk = 0; kk < 32; kk += 16) {
            int kg = ch*32 + kk;
            uint32_t Ah[4], Al[4];
            uint32_t offA = (uint32_t)(((m0 + (lane&15))*168
                                        + kg + ((lane>>4)<<3)) << 1);
            ldsm4(Ah, sb + offA);
            ldsm4(Al, sb + (uint32_t)(EPI_SL*2) + offA);
            int rB = kk + (lane&7) + (lane&8);
            frag_mma_row(acc, Ah, Al, stb, stbl, rB, 168, n0w, lane);
        }
        __syncthreads();
    }
    {   // split t into smem planes
        int r0l = wmi*16 + g;
        #pragma unroll
        for (int nt = 0; nt < 10; nt++) {
            int c0 = n0w + nt*8 + 2*t4;
            uint32_t wh, wl;
            split_pair(acc[nt][0], acc[nt][1], wh, wl);
            *(uint32_t*)(smb + EPI_TH + r0l*168 + c0) = wh;
            *(uint32_t*)(smb + EPI_TL + r0l*168 + c0) = wl;
            split_pair(acc[nt][2], acc[nt][3], wh, wl);
            *(uint32_t*)(smb + EPI_TH + (r0l+8)*168 + c0) = wh;
            *(uint32_t*)(smb + EPI_TL + (r0l+8)*168 + c0) = wl;
        }
    }
    __syncthreads();

    // ================= phase 2: a_new = t @ s (all smem) =================
    #pragma unroll
    for (int i = 0; i < 10; i++)
        acc[i][0] = acc[i][1] = acc[i][2] = acc[i][3] = 0.f;
    #pragma unroll
    for (int k16 = 0; k16 < 10; k16++) {
        int kg = k16*16;
        uint32_t Ah[4], Al[4];
        uint32_t offA = (uint32_t)(((wmi*16 + (lane&15))*168
                                    + kg + ((lane>>4)<<3)) << 1);
        ldsm4(Ah, sb + (uint32_t)(EPI_TH*2) + offA);
        ldsm4(Al, sb + (uint32_t)(EPI_TL*2) + offA);
        int rB = kg + (lane&7) + (lane&8);
        frag_mma_row(acc, Ah, Al, sb, sb + (uint32_t)(EPI_SL*2), rB, 168, n0w, lane);
    }
    {
        float* Aout = anew + (size_t)bc*NL;
        int r0 = m0 + g;
        #pragma unroll
        for (int nt = 0; nt < 10; nt++) {
            int c0 = n0w + nt*8 + 2*t4;
            *(float2*)&Aout[(size_t)r0*160 + c0]     = make_float2(acc[nt][0], acc[nt][1]);
            *(float2*)&Aout[(size_t)(r0+8)*160 + c0] = make_float2(acc[nt][2], acc[nt][3]);
        }
    }
}

// ============================================================
extern "C" void kernel_launch(void* const* d_in, const int* in_sizes, int n_in,
                              void* d_out, int out_size) {
    const float* x  = (const float*)d_in[0];
    const float* a  = (const float*)d_in[1];
    const float* We = (const float*)d_in[2];
    const float* be = (const float*)d_in[3];
    const float* Wp = (const float*)d_in[4];
    const float* bp = (const float*)d_in[5];
    float* out  = (float*)d_out;
    float* xnew = out;
    float* anew = out + (size_t)BC*NL;

    void *pMsh, *pMsl, *pxh, *pxl, *pyh, *pyl;
    cudaGetSymbolAddress(&pMsh, g_Msh); cudaGetSymbolAddress(&pMsl, g_Msl);
    cudaGetSymbolAddress(&pxh,  g_xh);  cudaGetSymbolAddress(&pxl,  g_xl);
    cudaGetSymbolAddress(&pyh,  g_yh);  cudaGetSymbolAddress(&pyl,  g_yl);

    cudaFuncSetAttribute((const void*)k_bgemm_bf,
        cudaFuncAttributeMaxDynamicSharedMemorySize, TGB::SMEM);
    cudaFuncSetAttribute((const void*)k_mix_bf,
        cudaFuncAttributeMaxDynamicSharedMemorySize, MIXB_SMEM);
    cudaFuncSetAttribute((const void*)k_softmax3,
        cudaFuncAttributeMaxDynamicSharedMemorySize, SMAX_SMEM);
    cudaFuncSetAttribute((const void*)k_epi,
        cudaFuncAttributeMaxDynamicSharedMemorySize, EPI_SMEM);

    k_norm_adj<<<Ndim, Ndim>>>(a);
    k_prep<<<dim3(5, 5), 64>>>();
    k_wcprep<<<(64*96 + 255)/256, 256>>>(We, Wp);
    k_xsplit<<<(int)(((size_t)BC*NL)/1024), 256>>>(x);

    // ystack = Ms @ x : A shared (sA=0), B = x planes, C = y planes (split)
    k_bgemm_bf<<<dim3(BC, 2, 2), 320, TGB::SMEM>>>(
        (const __nv_bfloat16*)pMsh, (const __nv_bfloat16*)pMsl, 0, Ndim,
        (const __nv_bfloat16*)pxh,  (const __nv_bfloat16*)pxl,  NL, Ndim,
        (__nv_bfloat16*)pyh, (__nv_bfloat16*)pyl, 2*NL, Ndim);

    // channel mix -> embed (split planes), pool (fp32)
    k_mix_bf<<<dim3(NL/160, Bdim), 320, MIXB_SMEM>>>(be, bp);

    k_softmax3<<<BC, Ndim, SMAX_SMEM>>>();

    // fused: x_new = s^T e ; t = s a ; a_new = t s
    k_epi<<<dim3(BC, 2), 320, EPI_SMEM>>>(xnew, anew);
}